// round 1
// baseline (speedup 1.0000x reference)
#include <cuda_runtime.h>
#include <cstdint>
#include <math_constants.h>

// MiniRocket fused dilated-conv + max/ppv, fp32 with packed f32x2 FMA.
// Shapes: x[16,12,5000], W[10,1000,12,9] (ternary), bias[10,1000].
// out[b, di*2000 + j]        = max_t conv(b,di,j,t)
// out[b, di*2000 + 1000 + j] = mean_t (conv > bias)
//
// Grid: (25 j-tiles, 16 batch, 10 dilations). Block: 256 threads
//   = 8 warps (each owns 5 kernels) x 32 lanes (each owns 4 time positions).
// Per time-tile of 128 positions, x is staged in SMEM as 9 shifted segments
// per channel (tap k of dilation d reads x[t + (k-4)d]), so the inner loop is
// pure LDS.128 + broadcast-LDS + FFMA2.

#define NTHREADS 256
#define TT 128          // time positions per tile
#define JB 40           // kernels per CTA
#define JT 5            // kernels per thread (8 warps * 5 = 40)

static_assert(JB * 25 == 1000, "j tiling");

__device__ __forceinline__ unsigned long long pk2(float lo, float hi) {
    unsigned long long r;
    asm("mov.b64 %0, {%1, %2};" : "=l"(r) : "f"(lo), "f"(hi));
    return r;
}
__device__ __forceinline__ void upk2(float& lo, float& hi, unsigned long long v) {
    asm("mov.b64 {%0, %1}, %2;" : "=f"(lo), "=f"(hi) : "l"(v));
}
__device__ __forceinline__ void ffma2(unsigned long long& d,
                                      unsigned long long a,
                                      unsigned long long b) {
    // d = a * b + d (two packed fp32 lanes)
    asm("fma.rn.f32x2 %0, %1, %2, %0;" : "+l"(d) : "l"(a), "l"(b));
}

// SMEM layout (floats): xs[12*9*TT] | sw[JB*108] | sb[JB]
#define XS_FLOATS (12 * 9 * TT)
#define SW_FLOATS (JB * 108)
#define SMEM_FLOATS (XS_FLOATS + SW_FLOATS + JB)
#define SMEM_BYTES (SMEM_FLOATS * 4)

__global__ void __launch_bounds__(NTHREADS, 2)
mrocket_kernel(const float* __restrict__ x,
               const float* __restrict__ W,
               const float* __restrict__ bias,
               float* __restrict__ out)
{
    const int jt = blockIdx.x;   // 0..24
    const int b  = blockIdx.y;   // 0..15
    const int di = blockIdx.z;   // 0..9
    const int d  = 1 << di;      // dilation: 1,2,4,...,512
    const int j0 = jt * JB;

    extern __shared__ float smem[];
    float* xs = smem;                 // [12][9][TT], tap-shifted x segments
    float* sw = xs + XS_FLOATS;       // [JB][108] weights tile
    float* sb = sw + SW_FLOATS;       // [JB] biases

    const int tid = threadIdx.x;
    const int tj  = tid >> 5;         // warp id 0..7 -> kernel group
    const int tt  = tid & 31;         // lane -> time group
    const int lt0 = tt << 2;          // local t base (4 per lane)

    // Stage weights + biases for this (dilation, j-tile)
    const float* Wd = W + (size_t)(di * 1000 + j0) * 108;
    for (int e = tid; e < SW_FLOATS; e += NTHREADS) sw[e] = Wd[e];
    if (tid < JB) sb[tid] = bias[di * 1000 + j0 + tid];
    __syncthreads();

    float bsr[JT];
    float vmax[JT];
    int   cnt[JT];
#pragma unroll
    for (int jj = 0; jj < JT; jj++) {
        bsr[jj]  = sb[tj * JT + jj];
        vmax[jj] = -CUDART_INF_F;
        cnt[jj]  = 0;
    }

    const float* xb = x + (size_t)b * 12 * 5000;

    for (int t0 = 0; t0 < 5000; t0 += TT) {
        __syncthreads();  // xs reuse barrier (and covers sb read on iter 0)

        // Load tap-shifted x segments: xs[(c*9+k)*TT + lt] = x[c, t0+lt+(k-4)d]
#pragma unroll 1
        for (int e = tid; e < XS_FLOATS; e += NTHREADS) {
            int lt = e & (TT - 1);
            int ck = e >> 7;          // TT == 128
            int c  = ck / 9;
            int k  = ck - c * 9;
            int g  = t0 + lt + (k - 4) * d;
            xs[e] = (g >= 0 && g < 5000) ? __ldg(&xb[c * 5000 + g]) : 0.0f;
        }
        __syncthreads();

        unsigned long long acc[JT][2];
#pragma unroll
        for (int jj = 0; jj < JT; jj++) { acc[jj][0] = 0ull; acc[jj][1] = 0ull; }

#pragma unroll 1
        for (int c = 0; c < 12; c++) {
            const float* swc = sw + (tj * JT) * 108 + c * 9;
#pragma unroll
            for (int k = 0; k < 9; k++) {
                float4 xv = *reinterpret_cast<const float4*>(
                    xs + (c * 9 + k) * TT + lt0);
                unsigned long long xlo = pk2(xv.x, xv.y);
                unsigned long long xhi = pk2(xv.z, xv.w);
#pragma unroll
                for (int jj = 0; jj < JT; jj++) {
                    float w = swc[jj * 108 + k];
                    unsigned long long w2 = pk2(w, w);
                    ffma2(acc[jj][0], w2, xlo);
                    ffma2(acc[jj][1], w2, xhi);
                }
            }
        }

        // Fused epilogue: running max / count(>bias) over this tile
        const int nvalid = 5000 - (t0 + lt0);  // valid t's for this lane
#pragma unroll
        for (int jj = 0; jj < JT; jj++) {
            float a0, a1, a2, a3;
            upk2(a0, a1, acc[jj][0]);
            upk2(a2, a3, acc[jj][1]);
            const float bv = bsr[jj];
            if (nvalid > 0) { vmax[jj] = fmaxf(vmax[jj], a0); cnt[jj] += (a0 > bv); }
            if (nvalid > 1) { vmax[jj] = fmaxf(vmax[jj], a1); cnt[jj] += (a1 > bv); }
            if (nvalid > 2) { vmax[jj] = fmaxf(vmax[jj], a2); cnt[jj] += (a2 > bv); }
            if (nvalid > 3) { vmax[jj] = fmaxf(vmax[jj], a3); cnt[jj] += (a3 > bv); }
        }
    }

    // Reduce across the 32 time-lanes of each warp; each warp owns distinct j's
#pragma unroll
    for (int jj = 0; jj < JT; jj++) {
        float m = vmax[jj];
        int   c = cnt[jj];
#pragma unroll
        for (int o = 16; o > 0; o >>= 1) {
            m  = fmaxf(m, __shfl_xor_sync(0xffffffffu, m, o));
            c += __shfl_xor_sync(0xffffffffu, c, o);
        }
        if (tt == 0) {
            int j = j0 + tj * JT + jj;
            float* ob = out + (size_t)b * 20000 + di * 2000;
            ob[j]        = m;
            ob[1000 + j] = (float)c * (1.0f / 5000.0f);
        }
    }
}

extern "C" void kernel_launch(void* const* d_in, const int* in_sizes, int n_in,
                              void* d_out, int out_size)
{
    const float* x    = (const float*)d_in[0];  // [16,12,5000]
    const float* W    = (const float*)d_in[1];  // [10,1000,12,9]
    const float* bias = (const float*)d_in[2];  // [10,1000]
    float* out = (float*)d_out;                 // [16,20000]

    cudaFuncSetAttribute(mrocket_kernel,
                         cudaFuncAttributeMaxDynamicSharedMemorySize,
                         SMEM_BYTES);

    dim3 grid(25, 16, 10);
    mrocket_kernel<<<grid, NTHREADS, SMEM_BYTES>>>(x, W, bias, out);
}